// round 1
// baseline (speedup 1.0000x reference)
// ELISSABETH round 0: correct baseline, tf32 mma.sync GEMMs + fused LISS scan.
// Pipeline: embed -> gates -> tf32 hi/lo splits -> V proj (gated epilogue)
//           -> 4-state recurrence -> W_O -> W_U (bias + transposed write).
#include <cuda_runtime.h>
#include <cstdint>

#define B_    2
#define T_    2048
#define DHID  1024
#define HH    512
#define NL    4
#define VOUT  32000
#define MTOT  (B_ * T_)   // 4096

// ---------------- scratch (device globals; no allocs allowed) ----------------
#define OFF_X     0LL                       // x:      4096 x 1024
#define OFF_XS    (OFF_X   + 4194304LL)     // xs:     4096 x 3072   (hi|hi|lo)
#define OFF_GATES (OFF_XS  + 12582912LL)    // gates:  5 x 4096
#define OFF_WVP   (OFF_GATES + 20480LL)     // WVp:    4 x 3072 x 512 (hi;lo;hi)
#define OFF_AV    (OFF_WVP + 6291456LL)     // AV:     4 x 4096 x 512 (gated V)
#define OFF_RS    (OFF_AV  + 8388608LL)     // Rsplit: 4096 x 1536   (hi|hi|lo)
#define OFF_WOP   (OFF_RS  + 6291456LL)     // WOp:    1536 x 1024   (hi;lo;hi)
#define OFF_Y     (OFF_WOP + 1572864LL)     // y:      4096 x 1024
#define SCRATCH_FLOATS (OFF_Y + 4194304LL)  // 43,536,384 floats (~174 MB)

__device__ __align__(256) float g_scratch[SCRATCH_FLOATS];

// ---------------- helpers ----------------
__device__ __forceinline__ uint32_t f2tf(float x) {
    uint32_t u; asm("cvt.rna.tf32.f32 %0, %1;" : "=r"(u) : "f"(x)); return u;
}
__device__ __forceinline__ float f2tff(float x) { return __uint_as_float(f2tf(x)); }

// ---------------- embed: x = emb[tok] + pos ----------------
__global__ void __launch_bounds__(256)
embed_kernel(const int* __restrict__ tokens, const float* __restrict__ emb,
             const float* __restrict__ pos, float* __restrict__ x)
{
    int m = blockIdx.x;            // 0..4095
    int t = m & (T_ - 1);
    int tok = tokens[m];
    int c = threadIdx.x * 4;       // 256 threads x float4 = 1024
    float4 e = *(const float4*)(emb + (long long)tok * DHID + c);
    float4 p = *(const float4*)(pos + (long long)t * DHID + c);
    *(float4*)(x + (long long)m * DHID + c) =
        make_float4(e.x + p.x, e.y + p.y, e.z + p.z, e.w + p.w);
}

// ---------------- gates: q,k scalar projections -> 5 exp gates per token ----
__global__ void __launch_bounds__(256)
gates_kernel(const float* __restrict__ x, const float* __restrict__ WQ,
             const float* __restrict__ WK, float* __restrict__ gates)
{
    int m = blockIdx.x;
    int tid = threadIdx.x, lane = tid & 31, w = tid >> 5;   // 8 warps: q0..3,k0..3
    const float* W  = (w < 4) ? (WQ + w * DHID) : (WK + (w - 4) * DHID);
    const float* xr = x + (long long)m * DHID;
    float p = 0.f;
    #pragma unroll
    for (int d = lane; d < DHID; d += 32) p += xr[d] * W[d];
    #pragma unroll
    for (int o = 16; o; o >>= 1) p += __shfl_xor_sync(0xFFFFFFFFu, p, o);
    __shared__ float s[8];
    if (lane == 0) s[w] = p;
    __syncthreads();
    if (tid == 0) {
        // s[0..3]=q0..3, s[4..7]=k0..3
        gates[0 * MTOT + m] = expf(-s[4]);          // layer 0:  exp(-k0)
        gates[1 * MTOT + m] = expf(s[0] - s[5]);    // exp(q0-k1)
        gates[2 * MTOT + m] = expf(s[1] - s[6]);    // exp(q1-k2)
        gates[3 * MTOT + m] = expf(s[2] - s[7]);    // exp(q2-k3)
        gates[4 * MTOT + m] = expf(s[3]);           // final:    exp(q3)
    }
}

// ---------------- tf32 hi/lo splits (K-concatenation trick) ----------------
// A-side rows: [hi | hi | lo]
__global__ void __launch_bounds__(256)
splitA_kernel(const float* __restrict__ in, float* __restrict__ out, int K)
{
    long long idx = (long long)blockIdx.x * blockDim.x + threadIdx.x;
    int m = (int)(idx / K), k = (int)(idx % K);
    float v  = in[idx];
    float hi = f2tff(v);
    float lo = f2tff(v - hi);
    float* o = out + (long long)m * 3 * K;
    o[k] = hi; o[K + k] = hi; o[2 * K + k] = lo;
}
// B-side rows: [hi ; lo ; hi]   (so Ah*Bh + Ah*Bl + Al*Bh = full precision)
__global__ void __launch_bounds__(256)
splitB_kernel(const float* __restrict__ in, float* __restrict__ out, int K, int N)
{
    long long idx = (long long)blockIdx.x * blockDim.x + threadIdx.x;
    long long kn = (long long)K * N;
    int z = (int)(idx / kn);
    long long r = idx - (long long)z * kn;
    int k = (int)(r / N), n = (int)(r % N);
    float v  = in[idx];
    float hi = f2tff(v);
    float lo = f2tff(v - hi);
    float* o = out + (long long)z * 3 * kn;
    o[(long long)k * N + n]            = hi;
    o[(long long)(K + k) * N + n]      = lo;
    o[(long long)(2 * K + k) * N + n]  = hi;
}

// ---------------- tf32 GEMM, 128x128x16 tile, m16n8k8 mma ----------------
// EPI 0: plain row-major C.  EPI 1: C *= gate[m] (per-layer z).  EPI 2: bias +
// transposed write C[v*M + m] (out is (B,V,T), M==T).
struct SmemGemm {
    union {
        struct { float A[2][128][20]; float B[2][16][136]; } mm;
        float ct[32][132];
    };
};

template<int EPI>
__global__ void __launch_bounds__(256)
gemm_tf32(const float* __restrict__ Ag, const float* __restrict__ Bg,
          float* __restrict__ Cg, const float* __restrict__ auxg,
          int M, int N, int K,
          long long sAz, long long sBz, long long sCz, long long sXz)
{
    __shared__ SmemGemm sm;
    const float* A  = Ag + sAz * blockIdx.z;
    const float* Bm = Bg + sBz * blockIdx.z;
    float*       C  = Cg + sCz * blockIdx.z;
    const float* aux = auxg ? (auxg + sXz * blockIdx.z) : nullptr;

    const int tid = threadIdx.x, lane = tid & 31, warp = tid >> 5;
    const int wm = (warp & 1) * 64, wn = (warp >> 1) * 32;
    const int m0 = blockIdx.x * 128, n0 = blockIdx.y * 128;

    float acc[4][4][4];
    #pragma unroll
    for (int i = 0; i < 4; ++i)
        #pragma unroll
        for (int j = 0; j < 4; ++j)
            #pragma unroll
            for (int r = 0; r < 4; ++r) acc[i][j][r] = 0.f;

    float4 pa[2], pb[2];

#define LOAD_TILE(kt) do {                                                        \
    int k0 = (kt) * 16;                                                           \
    _Pragma("unroll")                                                             \
    for (int it = 0; it < 2; ++it) {                                              \
        int q = tid + it * 256;                                                   \
        pa[it] = *(const float4*)(A  + (long long)(m0 + (q >> 2)) * K + k0 + (q & 3) * 4);  \
        pb[it] = *(const float4*)(Bm + (long long)(k0 + (q >> 5)) * N + n0 + (q & 31) * 4); \
    } } while (0)

#define STORE_TILE(buf) do {                                                      \
    _Pragma("unroll")                                                             \
    for (int it = 0; it < 2; ++it) {                                              \
        int q = tid + it * 256;                                                   \
        float4 va = pa[it];                                                       \
        *(float4*)&sm.mm.A[buf][q >> 2][(q & 3) * 4] =                            \
            make_float4(f2tff(va.x), f2tff(va.y), f2tff(va.z), f2tff(va.w));      \
        float4 vb = pb[it];                                                       \
        *(float4*)&sm.mm.B[buf][q >> 5][(q & 31) * 4] =                           \
            make_float4(f2tff(vb.x), f2tff(vb.y), f2tff(vb.z), f2tff(vb.w));      \
    } } while (0)

    const int KT = K >> 4;
    LOAD_TILE(0);
    STORE_TILE(0);
    __syncthreads();

    for (int kt = 0; kt < KT; ++kt) {
        int buf = kt & 1;
        if (kt + 1 < KT) LOAD_TILE(kt + 1);
        #pragma unroll
        for (int kk = 0; kk < 16; kk += 8) {
            uint32_t af[4][4], bf[4][2];
            #pragma unroll
            for (int i = 0; i < 4; ++i) {
                int lm = wm + i * 16 + (lane >> 2);
                int lk = kk + (lane & 3);
                af[i][0] = __float_as_uint(sm.mm.A[buf][lm][lk]);
                af[i][1] = __float_as_uint(sm.mm.A[buf][lm + 8][lk]);
                af[i][2] = __float_as_uint(sm.mm.A[buf][lm][lk + 4]);
                af[i][3] = __float_as_uint(sm.mm.A[buf][lm + 8][lk + 4]);
            }
            #pragma unroll
            for (int j = 0; j < 4; ++j) {
                int ln = wn + j * 8 + (lane >> 2);
                int lk = kk + (lane & 3);
                bf[j][0] = __float_as_uint(sm.mm.B[buf][lk][ln]);
                bf[j][1] = __float_as_uint(sm.mm.B[buf][lk + 4][ln]);
            }
            #pragma unroll
            for (int i = 0; i < 4; ++i)
                #pragma unroll
                for (int j = 0; j < 4; ++j)
                    asm volatile(
                        "mma.sync.aligned.m16n8k8.row.col.f32.tf32.tf32.f32 "
                        "{%0,%1,%2,%3}, {%4,%5,%6,%7}, {%8,%9}, {%0,%1,%2,%3};\n"
                        : "+f"(acc[i][j][0]), "+f"(acc[i][j][1]),
                          "+f"(acc[i][j][2]), "+f"(acc[i][j][3])
                        : "r"(af[i][0]), "r"(af[i][1]), "r"(af[i][2]), "r"(af[i][3]),
                          "r"(bf[j][0]), "r"(bf[j][1]));
        }
        if (kt + 1 < KT) STORE_TILE(buf ^ 1);
        __syncthreads();
    }
#undef LOAD_TILE
#undef STORE_TILE

    if (EPI == 0 || EPI == 1) {
        #pragma unroll
        for (int i = 0; i < 4; ++i) {
            int m = m0 + wm + i * 16 + (lane >> 2);
            float g0 = 1.f, g1 = 1.f;
            if (EPI == 1) { g0 = aux[m]; g1 = aux[m + 8]; }
            #pragma unroll
            for (int j = 0; j < 4; ++j) {
                int n = n0 + wn + j * 8 + (lane & 3) * 2;
                *(float2*)&C[(long long)m * N + n] =
                    make_float2(acc[i][j][0] * g0, acc[i][j][1] * g0);
                *(float2*)&C[(long long)(m + 8) * N + n] =
                    make_float2(acc[i][j][2] * g1, acc[i][j][3] * g1);
            }
        }
    } else {
        // transposed write through smem: out[v*M + m], +bias[v]
        #pragma unroll 1
        for (int ch = 0; ch < 4; ++ch) {
            if ((warp >> 1) == ch) {
                #pragma unroll
                for (int i = 0; i < 4; ++i)
                    #pragma unroll
                    for (int j = 0; j < 4; ++j) {
                        int ml = wm + i * 16 + (lane >> 2);
                        int nl = j * 8 + (lane & 3) * 2;
                        sm.ct[nl][ml]         = acc[i][j][0];
                        sm.ct[nl + 1][ml]     = acc[i][j][1];
                        sm.ct[nl][ml + 8]     = acc[i][j][2];
                        sm.ct[nl + 1][ml + 8] = acc[i][j][3];
                    }
            }
            __syncthreads();
            for (int q = tid; q < 32 * 128; q += 256) {
                int nl = q >> 7, ml = q & 127;
                int v = n0 + ch * 32 + nl;
                C[(long long)v * M + m0 + ml] = sm.ct[nl][ml] + aux[v];
            }
            __syncthreads();
        }
    }
}

// ---------------- fused LISS recurrence (4 states / lane, depth-8 prefetch) --
// AV[l][m][h] already gated; writes Rsplit rows [hi|hi|lo] directly.
__global__ void __launch_bounds__(128)
liss_kernel(const float* __restrict__ AV, const float* __restrict__ G4,
            float* __restrict__ R)
{
    const int b = blockIdx.y;
    const int h = blockIdx.x * 128 + threadIdx.x;
    const long long P = (long long)MTOT * HH;        // layer plane stride
    const float* base = AV + (long long)(b * T_) * HH + h;
    const float* g    = G4 + b * T_;
    float s0 = 0.f, s1 = 0.f, s2 = 0.f, s3 = 0.f;
    const int U = 8;
    float va[U][4], vg[U];
    #pragma unroll
    for (int u = 0; u < U; ++u) {
        #pragma unroll
        for (int l = 0; l < 4; ++l) va[u][l] = base[l * P + (long long)u * HH];
        vg[u] = g[u];
    }
    for (int t0 = 0; t0 < T_; t0 += U) {
        float nx[U][4], ng[U];
        const int tn = t0 + U;
        if (tn < T_) {
            #pragma unroll
            for (int u = 0; u < U; ++u) {
                #pragma unroll
                for (int l = 0; l < 4; ++l)
                    nx[u][l] = base[l * P + (long long)(tn + u) * HH];
                ng[u] = g[tn + u];
            }
        } else {
            #pragma unroll
            for (int u = 0; u < U; ++u) {
                ng[u] = 0.f;
                #pragma unroll
                for (int l = 0; l < 4; ++l) nx[u][l] = 0.f;
            }
        }
        #pragma unroll
        for (int u = 0; u < U; ++u) {
            // descending order: s_l uses s_{l-1} at (t-1)
            s3 += va[u][3] * s2;
            s2 += va[u][2] * s1;
            s1 += va[u][1] * s0;
            s0 += va[u][0];
            float r  = vg[u] * s3;
            float hi = f2tff(r);
            float lo = f2tff(r - hi);
            long long row = (long long)(b * T_ + t0 + u) * 1536;
            R[row + h]        = hi;
            R[row + 512 + h]  = hi;
            R[row + 1024 + h] = lo;
        }
        #pragma unroll
        for (int u = 0; u < U; ++u) {
            vg[u] = ng[u];
            #pragma unroll
            for (int l = 0; l < 4; ++l) va[u][l] = nx[u][l];
        }
    }
}

// ---------------- launch ----------------
extern "C" void kernel_launch(void* const* d_in, const int* in_sizes, int n_in,
                              void* d_out, int out_size)
{
    const int*   tokens = (const int*)  d_in[0];
    const float* emb    = (const float*)d_in[1];
    const float* pos    = (const float*)d_in[2];
    const float* WQ     = (const float*)d_in[3];
    const float* WK     = (const float*)d_in[4];
    const float* WV     = (const float*)d_in[5];
    const float* WO     = (const float*)d_in[6];
    const float* WU     = (const float*)d_in[7];
    const float* bU     = (const float*)d_in[8];
    float* out = (float*)d_out;

    float* S = nullptr;
    cudaGetSymbolAddress((void**)&S, g_scratch);
    float* x     = S + OFF_X;
    float* xs    = S + OFF_XS;
    float* gates = S + OFF_GATES;
    float* wvp   = S + OFF_WVP;
    float* av    = S + OFF_AV;
    float* rs    = S + OFF_RS;
    float* wop   = S + OFF_WOP;
    float* y     = S + OFF_Y;

    embed_kernel<<<MTOT, 256>>>(tokens, emb, pos, x);
    gates_kernel<<<MTOT, 256>>>(x, WQ, WK, gates);
    splitA_kernel<<<(MTOT * DHID) / 256, 256>>>(x, xs, DHID);
    splitB_kernel<<<(NL * DHID * HH) / 256, 256>>>(WV, wvp, DHID, HH);
    splitB_kernel<<<(HH * DHID) / 256, 256>>>(WO, wop, HH, DHID);

    // V projection (split K=3072), gated epilogue, planar per-layer output
    gemm_tf32<1><<<dim3(MTOT / 128, HH / 128, NL), 256>>>(
        xs, wvp, av, gates, MTOT, HH, 3 * DHID,
        0LL, (long long)3 * DHID * HH, (long long)MTOT * HH, (long long)MTOT);

    // recurrence -> Rsplit (hi|hi|lo)
    liss_kernel<<<dim3(HH / 128, B_), 128>>>(av, gates + 4LL * MTOT, rs);

    // W_O (split K=1536)
    gemm_tf32<0><<<dim3(MTOT / 128, DHID / 128, 1), 256>>>(
        rs, wop, y, nullptr, MTOT, DHID, 3 * HH, 0LL, 0LL, 0LL, 0LL);

    // W_U logits, bias + transposed (B,V,T) write; z = batch
    gemm_tf32<2><<<dim3(T_ / 128, VOUT / 128, B_), 256>>>(
        y, WU, out, bU, T_, VOUT, DHID,
        (long long)T_ * DHID, 0LL, (long long)VOUT * T_, 0LL);
}

// round 4
// speedup vs baseline: 1.1926x; 1.1926x over previous
// ELISSABETH round 3: bisection round — no tcgen05 (cannot hang), round-0
// legacy mma.sync path with hi/lo splits removed (single-pass tf32 all GEMMs,
// operands rounded in-kernel). embed -> gates -> V proj (gated) -> LISS ->
// W_O -> W_U (bias + transposed (B,V,T) write).
#include <cuda_runtime.h>
#include <cstdint>

#define B_    2
#define T_    2048
#define DHID  1024
#define HH    512
#define NL    4
#define VOUT  32000
#define MTOT  (B_ * T_)   // 4096

// ---------------- scratch (device globals; no allocs allowed) ----------------
#define OFF_X     0LL                       // x:      4096 x 1024
#define OFF_GATES (OFF_X + 4194304LL)       // gates:  5 x 4096
#define OFF_AV    (OFF_GATES + 20480LL)     // AV:     4 x 4096 x 512 (gated V)
#define OFF_RS    (OFF_AV + 8388608LL)      // R:      4096 x 512
#define OFF_Y     (OFF_RS + 2097152LL)      // y:      4096 x 1024
#define SCRATCH_FLOATS (OFF_Y + 4194304LL)  // ~18.9M floats (~76 MB)

__device__ __align__(256) float g_scratch[SCRATCH_FLOATS];

// ---------------- helpers ----------------
__device__ __forceinline__ uint32_t f2tf(float x) {
    uint32_t u; asm("cvt.rna.tf32.f32 %0, %1;" : "=r"(u) : "f"(x)); return u;
}
__device__ __forceinline__ float f2tff(float x) { return __uint_as_float(f2tf(x)); }

// ---------------- embed: x = emb[tok] + pos ----------------
__global__ void __launch_bounds__(256)
embed_kernel(const int* __restrict__ tokens, const float* __restrict__ emb,
             const float* __restrict__ pos, float* __restrict__ x)
{
    int m = blockIdx.x;            // 0..4095
    int t = m & (T_ - 1);
    int tok = tokens[m];
    int c = threadIdx.x * 4;       // 256 threads x float4 = 1024
    float4 e = *(const float4*)(emb + (long long)tok * DHID + c);
    float4 p = *(const float4*)(pos + (long long)t * DHID + c);
    *(float4*)(x + (long long)m * DHID + c) =
        make_float4(e.x + p.x, e.y + p.y, e.z + p.z, e.w + p.w);
}

// ---------------- gates: q,k scalar projections -> 5 exp gates per token ----
__global__ void __launch_bounds__(256)
gates_kernel(const float* __restrict__ x, const float* __restrict__ WQ,
             const float* __restrict__ WK, float* __restrict__ gates)
{
    int m = blockIdx.x;
    int tid = threadIdx.x, lane = tid & 31, w = tid >> 5;   // 8 warps: q0..3,k0..3
    const float* W  = (w < 4) ? (WQ + w * DHID) : (WK + (w - 4) * DHID);
    const float* xr = x + (long long)m * DHID;
    float p = 0.f;
    #pragma unroll
    for (int d = lane; d < DHID; d += 32) p += xr[d] * W[d];
    #pragma unroll
    for (int o = 16; o; o >>= 1) p += __shfl_xor_sync(0xFFFFFFFFu, p, o);
    __shared__ float s[8];
    if (lane == 0) s[w] = p;
    __syncthreads();
    if (tid == 0) {
        // s[0..3]=q0..3, s[4..7]=k0..3
        gates[0 * MTOT + m] = expf(-s[4]);          // layer 0:  exp(-k0)
        gates[1 * MTOT + m] = expf(s[0] - s[5]);    // exp(q0-k1)
        gates[2 * MTOT + m] = expf(s[1] - s[6]);    // exp(q1-k2)
        gates[3 * MTOT + m] = expf(s[2] - s[7]);    // exp(q2-k3)
        gates[4 * MTOT + m] = expf(s[3]);           // final:    exp(q3)
    }
}

// ---------------- tf32 GEMM, 128x128x16 tile, m16n8k8 mma ----------------
// EPI 0: plain row-major C.  EPI 1: C *= gate[m] (per-layer z).  EPI 2: bias +
// transposed write C[v*M + m] (out is (B,V,T), M==T).
struct SmemGemm {
    union {
        struct { float A[2][128][20]; float B[2][16][136]; } mm;
        float ct[32][132];
    };
};

template<int EPI>
__global__ void __launch_bounds__(256)
gemm_tf32(const float* __restrict__ Ag, const float* __restrict__ Bg,
          float* __restrict__ Cg, const float* __restrict__ auxg,
          int M, int N, int K,
          long long sAz, long long sBz, long long sCz, long long sXz)
{
    __shared__ SmemGemm sm;
    const float* A  = Ag + sAz * blockIdx.z;
    const float* Bm = Bg + sBz * blockIdx.z;
    float*       C  = Cg + sCz * blockIdx.z;
    const float* aux = auxg ? (auxg + sXz * blockIdx.z) : nullptr;

    const int tid = threadIdx.x, lane = tid & 31, warp = tid >> 5;
    const int wm = (warp & 1) * 64, wn = (warp >> 1) * 32;
    const int m0 = blockIdx.x * 128, n0 = blockIdx.y * 128;

    float acc[4][4][4];
    #pragma unroll
    for (int i = 0; i < 4; ++i)
        #pragma unroll
        for (int j = 0; j < 4; ++j)
            #pragma unroll
            for (int r = 0; r < 4; ++r) acc[i][j][r] = 0.f;

    float4 pa[2], pb[2];

#define LOAD_TILE(kt) do {                                                        \
    int k0 = (kt) * 16;                                                           \
    _Pragma("unroll")                                                             \
    for (int it = 0; it < 2; ++it) {                                              \
        int q = tid + it * 256;                                                   \
        pa[it] = *(const float4*)(A  + (long long)(m0 + (q >> 2)) * K + k0 + (q & 3) * 4);  \
        pb[it] = *(const float4*)(Bm + (long long)(k0 + (q >> 5)) * N + n0 + (q & 31) * 4); \
    } } while (0)

#define STORE_TILE(buf) do {                                                      \
    _Pragma("unroll")                                                             \
    for (int it = 0; it < 2; ++it) {                                              \
        int q = tid + it * 256;                                                   \
        float4 va = pa[it];                                                       \
        *(float4*)&sm.mm.A[buf][q >> 2][(q & 3) * 4] =                            \
            make_float4(f2tff(va.x), f2tff(va.y), f2tff(va.z), f2tff(va.w));      \
        float4 vb = pb[it];                                                       \
        *(float4*)&sm.mm.B[buf][q >> 5][(q & 31) * 4] =                           \
            make_float4(f2tff(vb.x), f2tff(vb.y), f2tff(vb.z), f2tff(vb.w));      \
    } } while (0)

    const int KT = K >> 4;
    LOAD_TILE(0);
    STORE_TILE(0);
    __syncthreads();

    for (int kt = 0; kt < KT; ++kt) {
        int buf = kt & 1;
        if (kt + 1 < KT) LOAD_TILE(kt + 1);
        #pragma unroll
        for (int kk = 0; kk < 16; kk += 8) {
            uint32_t af[4][4], bf[4][2];
            #pragma unroll
            for (int i = 0; i < 4; ++i) {
                int lm = wm + i * 16 + (lane >> 2);
                int lk = kk + (lane & 3);
                af[i][0] = __float_as_uint(sm.mm.A[buf][lm][lk]);
                af[i][1] = __float_as_uint(sm.mm.A[buf][lm + 8][lk]);
                af[i][2] = __float_as_uint(sm.mm.A[buf][lm][lk + 4]);
                af[i][3] = __float_as_uint(sm.mm.A[buf][lm + 8][lk + 4]);
            }
            #pragma unroll
            for (int j = 0; j < 4; ++j) {
                int ln = wn + j * 8 + (lane >> 2);
                int lk = kk + (lane & 3);
                bf[j][0] = __float_as_uint(sm.mm.B[buf][lk][ln]);
                bf[j][1] = __float_as_uint(sm.mm.B[buf][lk + 4][ln]);
            }
            #pragma unroll
            for (int i = 0; i < 4; ++i)
                #pragma unroll
                for (int j = 0; j < 4; ++j)
                    asm volatile(
                        "mma.sync.aligned.m16n8k8.row.col.f32.tf32.tf32.f32 "
                        "{%0,%1,%2,%3}, {%4,%5,%6,%7}, {%8,%9}, {%0,%1,%2,%3};\n"
                        : "+f"(acc[i][j][0]), "+f"(acc[i][j][1]),
                          "+f"(acc[i][j][2]), "+f"(acc[i][j][3])
                        : "r"(af[i][0]), "r"(af[i][1]), "r"(af[i][2]), "r"(af[i][3]),
                          "r"(bf[j][0]), "r"(bf[j][1]));
        }
        if (kt + 1 < KT) STORE_TILE(buf ^ 1);
        __syncthreads();
    }
#undef LOAD_TILE
#undef STORE_TILE

    if (EPI == 0 || EPI == 1) {
        #pragma unroll
        for (int i = 0; i < 4; ++i) {
            int m = m0 + wm + i * 16 + (lane >> 2);
            float g0 = 1.f, g1 = 1.f;
            if (EPI == 1) { g0 = aux[m]; g1 = aux[m + 8]; }
            #pragma unroll
            for (int j = 0; j < 4; ++j) {
                int n = n0 + wn + j * 8 + (lane & 3) * 2;
                *(float2*)&C[(long long)m * N + n] =
                    make_float2(acc[i][j][0] * g0, acc[i][j][1] * g0);
                *(float2*)&C[(long long)(m + 8) * N + n] =
                    make_float2(acc[i][j][2] * g1, acc[i][j][3] * g1);
            }
        }
    } else {
        // transposed write through smem: out[v*M + m], +bias[v]
        #pragma unroll 1
        for (int ch = 0; ch < 4; ++ch) {
            if ((warp >> 1) == ch) {
                #pragma unroll
                for (int i = 0; i < 4; ++i)
                    #pragma unroll
                    for (int j = 0; j < 4; ++j) {
                        int ml = wm + i * 16 + (lane >> 2);
                        int nl = j * 8 + (lane & 3) * 2;
                        sm.ct[nl][ml]         = acc[i][j][0];
                        sm.ct[nl + 1][ml]     = acc[i][j][1];
                        sm.ct[nl][ml + 8]     = acc[i][j][2];
                        sm.ct[nl + 1][ml + 8] = acc[i][j][3];
                    }
            }
            __syncthreads();
            for (int q = tid; q < 32 * 128; q += 256) {
                int nl = q >> 7, ml = q & 127;
                int v = n0 + ch * 32 + nl;
                C[(long long)v * M + m0 + ml] = sm.ct[nl][ml] + aux[v];
            }
            __syncthreads();
        }
    }
}

// ---------------- fused LISS recurrence (4 states / lane, depth-8 prefetch) --
// AV[l][m][h] already gated; writes R[m][h] = exp(q3) * s3 (plain fp32).
__global__ void __launch_bounds__(128)
liss_kernel(const float* __restrict__ AV, const float* __restrict__ G4,
            float* __restrict__ R)
{
    const int b = blockIdx.y;
    const int h = blockIdx.x * 128 + threadIdx.x;
    const long long P = (long long)MTOT * HH;        // layer plane stride
    const float* base = AV + (long long)(b * T_) * HH + h;
    const float* g    = G4 + b * T_;
    float s0 = 0.f, s1 = 0.f, s2 = 0.f, s3 = 0.f;
    const int U = 8;
    float va[U][4], vg[U];
    #pragma unroll
    for (int u = 0; u < U; ++u) {
        #pragma unroll
        for (int l = 0; l < 4; ++l) va[u][l] = base[l * P + (long long)u * HH];
        vg[u] = g[u];
    }
    for (int t0 = 0; t0 < T_; t0 += U) {
        float nx[U][4], ng[U];
        const int tn = t0 + U;
        if (tn < T_) {
            #pragma unroll
            for (int u = 0; u < U; ++u) {
                #pragma unroll
                for (int l = 0; l < 4; ++l)
                    nx[u][l] = base[l * P + (long long)(tn + u) * HH];
                ng[u] = g[tn + u];
            }
        } else {
            #pragma unroll
            for (int u = 0; u < U; ++u) {
                ng[u] = 0.f;
                #pragma unroll
                for (int l = 0; l < 4; ++l) nx[u][l] = 0.f;
            }
        }
        #pragma unroll
        for (int u = 0; u < U; ++u) {
            // descending order: s_l uses s_{l-1} at (t-1)
            s3 += va[u][3] * s2;
            s2 += va[u][2] * s1;
            s1 += va[u][1] * s0;
            s0 += va[u][0];
            R[(long long)(b * T_ + t0 + u) * HH + h] = vg[u] * s3;
        }
        #pragma unroll
        for (int u = 0; u < U; ++u) {
            vg[u] = ng[u];
            #pragma unroll
            for (int l = 0; l < 4; ++l) va[u][l] = nx[u][l];
        }
    }
}

// ---------------- launch ----------------
extern "C" void kernel_launch(void* const* d_in, const int* in_sizes, int n_in,
                              void* d_out, int out_size)
{
    const int*   tokens = (const int*)  d_in[0];
    const float* emb    = (const float*)d_in[1];
    const float* pos    = (const float*)d_in[2];
    const float* WQ     = (const float*)d_in[3];
    const float* WK     = (const float*)d_in[4];
    const float* WV     = (const float*)d_in[5];
    const float* WO     = (const float*)d_in[6];
    const float* WU     = (const float*)d_in[7];
    const float* bU     = (const float*)d_in[8];
    float* out = (float*)d_out;

    float* S = nullptr;
    cudaGetSymbolAddress((void**)&S, g_scratch);
    float* x     = S + OFF_X;
    float* gates = S + OFF_GATES;
    float* av    = S + OFF_AV;
    float* rs    = S + OFF_RS;
    float* y     = S + OFF_Y;

    embed_kernel<<<MTOT, 256>>>(tokens, emb, pos, x);
    gates_kernel<<<MTOT, 256>>>(x, WQ, WK, gates);

    // V projection (K=1024, single-pass tf32), gated epilogue, per-layer planes
    gemm_tf32<1><<<dim3(MTOT / 128, HH / 128, NL), 256>>>(
        x, WV, av, gates, MTOT, HH, DHID,
        0LL, (long long)DHID * HH, (long long)MTOT * HH, (long long)MTOT);

    // recurrence -> R (fp32; GEMM rounds operands on smem store)
    liss_kernel<<<dim3(HH / 128, B_), 128>>>(av, gates + 4LL * MTOT, rs);

    // W_O (K=512)
    gemm_tf32<0><<<dim3(MTOT / 128, DHID / 128, 1), 256>>>(
        rs, WO, y, nullptr, MTOT, DHID, HH, 0LL, 0LL, 0LL, 0LL);

    // W_U logits (K=1024), bias + transposed (B,V,T) write; z = batch
    gemm_tf32<2><<<dim3(T_ / 128, VOUT / 128, B_), 256>>>(
        y, WU, out, bU, T_, VOUT, DHID,
        (long long)T_ * DHID, 0LL, (long long)VOUT * T_, 0LL);
}